// round 6
// baseline (speedup 1.0000x reference)
#include <cuda_runtime.h>
#include <math.h>

// Problem constants
#define LL    6
#define BSZ   8
#define FCH   32
#define MAPD  125
#define LOCD  25
#define NA    8
#define NPIX  (MAPD*MAPD)   // 15625
#define KSZ   (LOCD*LOCD)   // 625

// Conv tiling: 16 output rows per block (two warp-groups x 4 row-pairs), halo 24
#define TYB   16            // rows per block
#define NYT   8             // ceil(125/16)
#define TROWS 40            // TYB + 24
#define TC2   152           // 149 cols padded

// smem: duplicated weights [k][4 co-pairs] (625*4*16B = 40000) + tile pairs (48640)
#define WTS_BYTES (KSZ*4*16)
#define CONV_SMEM (WTS_BYTES + TROWS*TC2*8)   // 40000 + 48640 = 88640 B

// Scratch (device globals; no allocation allowed)
__device__ float g_rot[LL*BSZ*NA*FCH*KSZ];     // rotated tiles [l][b][a][f][25][25]
__device__ float g_oreg[BSZ*FCH*NPIX];         // conv1 output (GRU input)
__device__ float g_msm[BSZ*(FCH-1)*NPIX];      // channel-softmaxed maps, ch 1..31
__device__ float g_scoresP[4][BSZ*NA*NPIX];    // conv2 partial outputs (4 channel splits)

// Packed fp32x2 FMA (Blackwell FFMA2 — only reachable via PTX)
#define FMA2(d, a, b) \
    asm("fma.rn.f32x2 %0, %1, %2, %3;" : "=l"(d) : "l"(a), "l"(b), "l"(d))
#define UNPACK2(lo, hi, d) \
    asm("mov.b64 {%0, %1}, %2;" : "=f"(lo), "=f"(hi) : "l"(d))

// ---------------------------------------------------------------------------
// Rotation resample: image_cls (L,BS,F,25,25) -> g_rot (L,BS,A,F,25,25)
// ---------------------------------------------------------------------------
__global__ void resample_kernel(const float* __restrict__ img)
{
    int idx = blockIdx.x * blockDim.x + threadIdx.x;
    const int total = LL*BSZ*NA*FCH*KSZ;
    if (idx >= total) return;

    int xx = idx % LOCD;
    int yy = (idx / LOCD) % LOCD;
    int f  = (idx / KSZ) % FCH;
    int a  = (idx / (KSZ*FCH)) % NA;
    int lb = idx / (KSZ*FCH*NA);

    float gx = -1.0f + (float)xx * (2.0f/24.0f);
    float gy = -1.0f + (float)yy * (2.0f/24.0f);
    float ang = (float)a * 0.78539816339744830961f;
    float sn, c;
    sincosf(ang, &sn, &c);
    float px = (c*gx - sn*gy + 1.0f) * 12.0f;
    float py = (sn*gx + c*gy + 1.0f) * 12.0f;

    int x0 = (int)floorf(px);
    int y0 = (int)floorf(py);
    float wx1 = px - (float)x0, wy1 = py - (float)y0;
    float wx0 = 1.0f - wx1,     wy0 = 1.0f - wy1;

    const float* im = img + (lb*FCH + f)*KSZ;
    float v00 = (y0   >= 0 && y0   < LOCD && x0   >= 0 && x0   < LOCD) ? im[y0*LOCD + x0]       : 0.0f;
    float v01 = (y0   >= 0 && y0   < LOCD && x0+1 >= 0 && x0+1 < LOCD) ? im[y0*LOCD + x0+1]     : 0.0f;
    float v10 = (y0+1 >= 0 && y0+1 < LOCD && x0   >= 0 && x0   < LOCD) ? im[(y0+1)*LOCD + x0]   : 0.0f;
    float v11 = (y0+1 >= 0 && y0+1 < LOCD && x0+1 >= 0 && x0+1 < LOCD) ? im[(y0+1)*LOCD + x0+1] : 0.0f;

    g_rot[idx] = v00*wy0*wx0 + v01*wy0*wx1 + v10*wy1*wx0 + v11*wy1*wx1;
}

// ---------------------------------------------------------------------------
// conv1 at t=0: p0 is a delta at (a=0, y=62, x=62) -> just stamp rot[0,b,0,f]
// ---------------------------------------------------------------------------
__global__ void conv1_t0_kernel()
{
    int idx = blockIdx.x * blockDim.x + threadIdx.x;
    if (idx >= BSZ*FCH*NPIX) return;
    int x  = idx % MAPD;
    int y  = (idx / MAPD) % MAPD;
    int f  = (idx / NPIX) % FCH;
    int b  = idx / (NPIX*FCH);
    float v = 0.0f;
    if (y >= 50 && y <= 74 && x >= 50 && x <= 74)
        v = g_rot[((b*NA + 0)*FCH + f)*KSZ + (y-50)*LOCD + (x-50)];
    g_oreg[idx] = v;
}

// ---------------------------------------------------------------------------
// conv1 (write-memory), t>=1:
// o_reg[b,f,y,x] = sum_{a,j,i} rot[t,b,a,f,j,i] * p[b,a,y+12-j,x+12-i]
// block = (ytile16, co-group of 8, b); 256 threads (2 warp-groups share tile+wts)
// Weights pre-duplicated in smem as [k][4 co-pair float4] for LDS.128 broadcast.
// ---------------------------------------------------------------------------
__global__ __launch_bounds__(256)
void conv1_kernel(int t, const float* __restrict__ psrc)
{
    extern __shared__ float smem[];
    float4* wtsv = (float4*)smem;                        // [KSZ][4] : (w,w,w',w')
    const ulonglong2* wtsu = (const ulonglong2*)smem;    // 1 ulonglong2 == 1 float4
    float2* pt2 = (float2*)(smem + WTS_BYTES/4);         // [TROWS][TC2] row-pairs
    const unsigned long long* pt64 = (const unsigned long long*)pt2;

    const int tid = threadIdx.x;
    const int wg  = tid >> 7;                    // warp-group 0/1
    const int wt  = tid & 127;
    const int yt  = blockIdx.x;
    const int cg  = blockIdx.y;                  // 0..3
    const int b   = blockIdx.z;
    const int y0  = yt * TYB;

    const float* rot_t = g_rot + t * (BSZ*NA*FCH*KSZ);

    unsigned long long acc[4][8];
#pragma unroll
    for (int s = 0; s < 4; s++)
#pragma unroll
        for (int co = 0; co < 8; co++) acc[s][co] = 0ULL;

    for (int a = 0; a < NA; a++) {
        __syncthreads();
        const float* ps = psrc + (b*NA + a)*NPIX;
        for (int i = tid; i < TROWS*TC2; i += 256) {
            int rr = i / TC2, cc = i % TC2;
            int gy = y0 + rr - 12, gx = cc - 12;
            float2 v;
            v.x = (gy   >= 0 && gy   < MAPD && gx >= 0 && gx < MAPD) ? ps[gy*MAPD + gx]     : 0.0f;
            v.y = (gy+1 >= 0 && gy+1 < MAPD && gx >= 0 && gx < MAPD) ? ps[(gy+1)*MAPD + gx] : 0.0f;
            pt2[i] = v;
        }
        // weights: transpose to [k][co-pair], duplicated
        const float* ws = rot_t + ((b*NA + a)*FCH + cg*8)*KSZ;
        for (int i = tid; i < KSZ*4; i += 256) {
            int k = i >> 2, cp = i & 3;
            float w0 = ws[(2*cp)*KSZ + k];
            float w1 = ws[(2*cp+1)*KSZ + k];
            wtsv[i] = make_float4(w0, w0, w1, w1);
        }
        __syncthreads();

        if (wt < MAPD) {
            for (int j = 0; j < LOCD; j++) {
                int kbase = j*LOCD;
                int pidx0 = (24 - j + wg*8)*TC2 + wt + 24;
#pragma unroll 5
                for (int i = 0; i < LOCD; i++) {
                    unsigned long long pv[4];
#pragma unroll
                    for (int s = 0; s < 4; s++)
                        pv[s] = pt64[pidx0 - i + s*(2*TC2)];
                    const ulonglong2* wv = wtsu + (kbase + i)*4;   // 4 float4 per k
                    ulonglong2 w01 = wv[0];
                    ulonglong2 w23 = wv[1];
#pragma unroll
                    for (int s = 0; s < 4; s++) {
                        FMA2(acc[s][0], pv[s], w01.x);
                        FMA2(acc[s][1], pv[s], w01.y);
                        FMA2(acc[s][2], pv[s], w23.x);
                        FMA2(acc[s][3], pv[s], w23.y);
                    }
                    ulonglong2 w45 = wv[2];
                    ulonglong2 w67 = wv[3];
#pragma unroll
                    for (int s = 0; s < 4; s++) {
                        FMA2(acc[s][4], pv[s], w45.x);
                        FMA2(acc[s][5], pv[s], w45.y);
                        FMA2(acc[s][6], pv[s], w67.x);
                        FMA2(acc[s][7], pv[s], w67.y);
                    }
                }
            }
        }
    }

    if (wt < MAPD) {
#pragma unroll
        for (int co = 0; co < 8; co++)
#pragma unroll
            for (int s = 0; s < 4; s++) {
                float lo, hi;
                UNPACK2(lo, hi, acc[s][co]);
                int y = y0 + wg*8 + 2*s;
                float* dst = g_oreg + (b*FCH + cg*8 + co)*NPIX + y*MAPD + wt;
                if (y   < MAPD) dst[0]    = lo;
                if (y+1 < MAPD) dst[MAPD] = hi;
            }
    }
}

// ---------------------------------------------------------------------------
// GRU cell per pixel + channel softmax.
// ---------------------------------------------------------------------------
__global__ __launch_bounds__(128)
void gru_kernel(const float* __restrict__ hprev,
                const float* __restrict__ w_ih, const float* __restrict__ w_hh,
                const float* __restrict__ b_ih, const float* __restrict__ b_hh,
                float* __restrict__ mout)
{
    __shared__ float4 s_wih[96*8];
    __shared__ float4 s_whh[96*8];
    __shared__ float  s_b[192];

    const int tid = threadIdx.x;
    const float4* wi4 = (const float4*)w_ih;
    const float4* wh4 = (const float4*)w_hh;
    for (int i = tid; i < 96*8; i += 128) { s_wih[i] = wi4[i]; s_whh[i] = wh4[i]; }
    if (tid < 96) { s_b[tid] = b_ih[tid]; s_b[96+tid] = b_hh[tid]; }
    __syncthreads();

    const int pix = blockIdx.x * 128 + tid;
    if (pix >= NPIX) return;
    const int b = blockIdx.y;

    float x[32], h[32];
#pragma unroll
    for (int c = 0; c < 32; c++) {
        x[c] = g_oreg[(b*FCH + c)*NPIX + pix];
        h[c] = hprev[(b*FCH + c)*NPIX + pix];
    }

    float mx = -1e30f;
    float mvals[32];
    for (int c = 0; c < 32; c++) {
        float accr = s_b[c]      + s_b[96+c];
        float accz = s_b[32+c]   + s_b[128+c];
        float acci = s_b[64+c];
        float acch = s_b[160+c];
        const float4* wr_i = s_wih + c*8;
        const float4* wz_i = s_wih + (32+c)*8;
        const float4* wn_i = s_wih + (64+c)*8;
        const float4* wr_h = s_whh + c*8;
        const float4* wz_h = s_whh + (32+c)*8;
        const float4* wn_h = s_whh + (64+c)*8;
#pragma unroll
        for (int k = 0; k < 8; k++) {
            float4 wv;
            wv = wr_i[k]; accr += wv.x*x[4*k] + wv.y*x[4*k+1] + wv.z*x[4*k+2] + wv.w*x[4*k+3];
            wv = wr_h[k]; accr += wv.x*h[4*k] + wv.y*h[4*k+1] + wv.z*h[4*k+2] + wv.w*h[4*k+3];
            wv = wz_i[k]; accz += wv.x*x[4*k] + wv.y*x[4*k+1] + wv.z*x[4*k+2] + wv.w*x[4*k+3];
            wv = wz_h[k]; accz += wv.x*h[4*k] + wv.y*h[4*k+1] + wv.z*h[4*k+2] + wv.w*h[4*k+3];
            wv = wn_i[k]; acci += wv.x*x[4*k] + wv.y*x[4*k+1] + wv.z*x[4*k+2] + wv.w*x[4*k+3];
            wv = wn_h[k]; acch += wv.x*h[4*k] + wv.y*h[4*k+1] + wv.z*h[4*k+2] + wv.w*h[4*k+3];
        }
        float r = 1.0f/(1.0f + expf(-accr));
        float z = 1.0f/(1.0f + expf(-accz));
        float n = tanhf(acci + r*acch);
        float mv = (1.0f - z)*n + z*h[c];
        mvals[c] = mv;
        mout[(b*FCH + c)*NPIX + pix] = mv;
        mx = fmaxf(mx, mv);
    }

    float sum = 0.0f;
    float e[32];
#pragma unroll
    for (int c = 0; c < 32; c++) { e[c] = expf(mvals[c] - mx); sum += e[c]; }
    float inv = 1.0f / sum;
#pragma unroll
    for (int c = 1; c < 32; c++)
        g_msm[(b*(FCH-1) + (c-1))*NPIX + pix] = e[c] * inv;
}

// ---------------------------------------------------------------------------
// conv2 (localize): scores[b,a,y,x] = sum_{c,ky,kx}
//    msm[b,c,y+ky-12,x+kx-12] * rot[t+1,b,a,c+1,ky,kx]
// block = (ytile16, channel-split q, b); 256 threads; predup weights
// ---------------------------------------------------------------------------
__global__ __launch_bounds__(256)
void conv2_kernel(int t)
{
    extern __shared__ float smem[];
    float4* wtsv = (float4*)smem;
    const ulonglong2* wtsu = (const ulonglong2*)smem;
    float2* pt2 = (float2*)(smem + WTS_BYTES/4);
    const unsigned long long* pt64 = (const unsigned long long*)pt2;

    const int tid = threadIdx.x;
    const int wg  = tid >> 7;
    const int wt  = tid & 127;
    const int yt  = blockIdx.x;
    const int q   = blockIdx.y;                  // 0..3
    const int b   = blockIdx.z;
    const int y0  = yt * TYB;
    const int c0  = q * 8;
    int c1 = c0 + 8;
    if (c1 > FCH-1) c1 = FCH-1;

    const float* rot_n = g_rot + (t+1) * (BSZ*NA*FCH*KSZ);

    unsigned long long acc[4][8];
#pragma unroll
    for (int s = 0; s < 4; s++)
#pragma unroll
        for (int a = 0; a < 8; a++) acc[s][a] = 0ULL;

    for (int c = c0; c < c1; c++) {
        __syncthreads();
        const float* ps = g_msm + (b*(FCH-1) + c)*NPIX;
        for (int i = tid; i < TROWS*TC2; i += 256) {
            int rr = i / TC2, cc = i % TC2;
            int gy = y0 + rr - 12, gx = cc - 12;
            float2 v;
            v.x = (gy   >= 0 && gy   < MAPD && gx >= 0 && gx < MAPD) ? ps[gy*MAPD + gx]     : 0.0f;
            v.y = (gy+1 >= 0 && gy+1 < MAPD && gx >= 0 && gx < MAPD) ? ps[(gy+1)*MAPD + gx] : 0.0f;
            pt2[i] = v;
        }
        // weights: angle a plays the "co" role; transpose to [k][a-pair], dup
        const float* wbase = rot_n + (b*NA*FCH + (c+1))*KSZ;
        for (int i = tid; i < KSZ*4; i += 256) {
            int k = i >> 2, ap = i & 3;
            float w0 = wbase[(2*ap)*FCH*KSZ + k];
            float w1 = wbase[(2*ap+1)*FCH*KSZ + k];
            wtsv[i] = make_float4(w0, w0, w1, w1);
        }
        __syncthreads();

        if (wt < MAPD) {
            for (int ky = 0; ky < LOCD; ky++) {
                int kbase = ky*LOCD;
                int pidx0 = (ky + wg*8)*TC2 + wt;
#pragma unroll 5
                for (int kx = 0; kx < LOCD; kx++) {
                    unsigned long long pv[4];
#pragma unroll
                    for (int s = 0; s < 4; s++)
                        pv[s] = pt64[pidx0 + kx + s*(2*TC2)];
                    const ulonglong2* wv = wtsu + (kbase + kx)*4;   // 4 float4 per k
                    ulonglong2 w01 = wv[0];
                    ulonglong2 w23 = wv[1];
#pragma unroll
                    for (int s = 0; s < 4; s++) {
                        FMA2(acc[s][0], pv[s], w01.x);
                        FMA2(acc[s][1], pv[s], w01.y);
                        FMA2(acc[s][2], pv[s], w23.x);
                        FMA2(acc[s][3], pv[s], w23.y);
                    }
                    ulonglong2 w45 = wv[2];
                    ulonglong2 w67 = wv[3];
#pragma unroll
                    for (int s = 0; s < 4; s++) {
                        FMA2(acc[s][4], pv[s], w45.x);
                        FMA2(acc[s][5], pv[s], w45.y);
                        FMA2(acc[s][6], pv[s], w67.x);
                        FMA2(acc[s][7], pv[s], w67.y);
                    }
                }
            }
        }
    }

    if (wt < MAPD) {
#pragma unroll
        for (int a = 0; a < 8; a++)
#pragma unroll
            for (int s = 0; s < 4; s++) {
                float lo, hi;
                UNPACK2(lo, hi, acc[s][a]);
                int y = y0 + wg*8 + 2*s;
                float* dst = g_scoresP[q] + (b*NA + a)*NPIX + y*MAPD + wt;
                if (y   < MAPD) dst[0]    = lo;
                if (y+1 < MAPD) dst[MAPD] = hi;
            }
    }
}

// ---------------------------------------------------------------------------
// Global softmax over (A,H,W), summing the 4 conv2 partials.
// ---------------------------------------------------------------------------
__global__ void softmax_pose_kernel(float* __restrict__ pdst)
{
    const int b = blockIdx.x;
    const int base = b*NA*NPIX;
    float* o = pdst + base;
    const int N = NA*NPIX;
    __shared__ float red[33];
    const int tid = threadIdx.x;

    float mx = -1e30f;
    for (int i = tid; i < N; i += 1024) {
        float s = g_scoresP[0][base+i] + g_scoresP[1][base+i]
                + g_scoresP[2][base+i] + g_scoresP[3][base+i];
        mx = fmaxf(mx, s);
    }
#pragma unroll
    for (int off = 16; off; off >>= 1) mx = fmaxf(mx, __shfl_xor_sync(0xffffffffu, mx, off));
    if ((tid & 31) == 0) red[tid >> 5] = mx;
    __syncthreads();
    if (tid < 32) {
        float v = red[tid];
#pragma unroll
        for (int off = 16; off; off >>= 1) v = fmaxf(v, __shfl_xor_sync(0xffffffffu, v, off));
        if (tid == 0) red[32] = v;
    }
    __syncthreads();
    mx = red[32];
    __syncthreads();

    float sum = 0.0f;
    for (int i = tid; i < N; i += 1024) {
        float s = g_scoresP[0][base+i] + g_scoresP[1][base+i]
                + g_scoresP[2][base+i] + g_scoresP[3][base+i];
        sum += expf(s - mx);
    }
#pragma unroll
    for (int off = 16; off; off >>= 1) sum += __shfl_xor_sync(0xffffffffu, sum, off);
    if ((tid & 31) == 0) red[tid >> 5] = sum;
    __syncthreads();
    if (tid < 32) {
        float v = red[tid];
#pragma unroll
        for (int off = 16; off; off >>= 1) v += __shfl_xor_sync(0xffffffffu, v, off);
        if (tid == 0) red[32] = v;
    }
    __syncthreads();
    float inv = 1.0f / red[32];

    for (int i = tid; i < N; i += 1024) {
        float s = g_scoresP[0][base+i] + g_scoresP[1][base+i]
                + g_scoresP[2][base+i] + g_scoresP[3][base+i];
        o[i] = expf(s - mx) * inv;
    }
}

// ---------------------------------------------------------------------------
// Host launcher (graph-capturable, allocation-free).
// Output: poses_all (5,8,8,125,125) | maps_all (5,8,32,125,125) | m_final (8,32,125,125)
// ---------------------------------------------------------------------------
extern "C" void kernel_launch(void* const* d_in, const int* in_sizes, int n_in,
                              void* d_out, int out_size)
{
    const float* img   = (const float*)d_in[0];
    const float* maps0 = (const float*)d_in[1];
    const float* w_ih  = (const float*)d_in[3];
    const float* w_hh  = (const float*)d_in[4];
    const float* b_ih  = (const float*)d_in[5];
    const float* b_hh  = (const float*)d_in[6];

    float* out   = (float*)d_out;
    float* poses = out;
    float* mapso = out + 5*BSZ*NA*NPIX;
    float* mfin  = out + 5*BSZ*NA*NPIX + 5*BSZ*FCH*NPIX;

    cudaFuncSetAttribute(conv1_kernel, cudaFuncAttributeMaxDynamicSharedMemorySize, CONV_SMEM);
    cudaFuncSetAttribute(conv2_kernel, cudaFuncAttributeMaxDynamicSharedMemorySize, CONV_SMEM);

    resample_kernel<<<(LL*BSZ*NA*FCH*KSZ + 255)/256, 256>>>(img);

    for (int t = 0; t < LL-1; t++) {
        const float* hsrc = (t == 0) ? maps0 : (mapso + (t-1)*BSZ*FCH*NPIX);
        float* mdst = mapso + t*BSZ*FCH*NPIX;
        float* pdst = poses + t*BSZ*NA*NPIX;

        if (t == 0) {
            conv1_t0_kernel<<<(BSZ*FCH*NPIX + 255)/256, 256>>>();
        } else {
            const float* psrc = poses + (t-1)*BSZ*NA*NPIX;
            conv1_kernel<<<dim3(NYT, 4, BSZ), 256, CONV_SMEM>>>(t, psrc);
        }
        gru_kernel<<<dim3((NPIX + 127)/128, BSZ), 128>>>(hsrc, w_ih, w_hh, b_ih, b_hh, mdst);
        conv2_kernel<<<dim3(NYT, 4, BSZ), 256, CONV_SMEM>>>(t);
        softmax_pose_kernel<<<BSZ, 1024>>>(pdst);
    }

    cudaMemcpyAsync(mfin, mapso + 4*BSZ*FCH*NPIX,
                    (size_t)BSZ*FCH*NPIX*sizeof(float),
                    cudaMemcpyDeviceToDevice);
}

// round 7
// speedup vs baseline: 1.0011x; 1.0011x over previous
#include <cuda_runtime.h>
#include <math.h>

// Problem constants
#define LL    6
#define BSZ   8
#define FCH   32
#define MAPD  125
#define LOCD  25
#define NA    8
#define NPIX  (MAPD*MAPD)   // 15625
#define KSZ   (LOCD*LOCD)   // 625

// Conv tiling: 16 output rows per block (two warp-groups x 4 row-pairs), halo 24
#define TYB   16            // rows per block
#define NYT   8             // ceil(125/16)
#define TROWS 40            // TYB + 24
#define TC2   152           // 149 cols padded

// smem: duplicated weights [k][4 co-pairs] (625*4*16B = 40000) + tile pairs (48640)
#define WTS_BYTES (KSZ*4*16)
#define CONV_SMEM (WTS_BYTES + TROWS*TC2*8)   // 40000 + 48640 = 88640 B

// Scratch (device globals; no allocation allowed)
__device__ float g_rot[LL*BSZ*NA*FCH*KSZ];     // rotated tiles [l][b][a][f][25][25]
__device__ float g_oreg[BSZ*FCH*NPIX];         // conv1 output (GRU input)
__device__ float g_msm[BSZ*(FCH-1)*NPIX];      // channel-softmaxed maps, ch 1..31
__device__ float g_scoresP[4][BSZ*NA*NPIX];    // conv2 partial outputs (4 channel splits)

// Packed fp32x2 FMA (Blackwell FFMA2 — only reachable via PTX)
#define FMA2(d, a, b) \
    asm("fma.rn.f32x2 %0, %1, %2, %3;" : "=l"(d) : "l"(a), "l"(b), "l"(d))
#define UNPACK2(lo, hi, d) \
    asm("mov.b64 {%0, %1}, %2;" : "=f"(lo), "=f"(hi) : "l"(d))

// ---------------------------------------------------------------------------
// Rotation resample: image_cls (L,BS,F,25,25) -> g_rot (L,BS,A,F,25,25)
// ---------------------------------------------------------------------------
__global__ void resample_kernel(const float* __restrict__ img)
{
    int idx = blockIdx.x * blockDim.x + threadIdx.x;
    const int total = LL*BSZ*NA*FCH*KSZ;
    if (idx >= total) return;

    int xx = idx % LOCD;
    int yy = (idx / LOCD) % LOCD;
    int f  = (idx / KSZ) % FCH;
    int a  = (idx / (KSZ*FCH)) % NA;
    int lb = idx / (KSZ*FCH*NA);

    float gx = -1.0f + (float)xx * (2.0f/24.0f);
    float gy = -1.0f + (float)yy * (2.0f/24.0f);
    float ang = (float)a * 0.78539816339744830961f;
    float sn, c;
    sincosf(ang, &sn, &c);
    float px = (c*gx - sn*gy + 1.0f) * 12.0f;
    float py = (sn*gx + c*gy + 1.0f) * 12.0f;

    int x0 = (int)floorf(px);
    int y0 = (int)floorf(py);
    float wx1 = px - (float)x0, wy1 = py - (float)y0;
    float wx0 = 1.0f - wx1,     wy0 = 1.0f - wy1;

    const float* im = img + (lb*FCH + f)*KSZ;
    float v00 = (y0   >= 0 && y0   < LOCD && x0   >= 0 && x0   < LOCD) ? im[y0*LOCD + x0]       : 0.0f;
    float v01 = (y0   >= 0 && y0   < LOCD && x0+1 >= 0 && x0+1 < LOCD) ? im[y0*LOCD + x0+1]     : 0.0f;
    float v10 = (y0+1 >= 0 && y0+1 < LOCD && x0   >= 0 && x0   < LOCD) ? im[(y0+1)*LOCD + x0]   : 0.0f;
    float v11 = (y0+1 >= 0 && y0+1 < LOCD && x0+1 >= 0 && x0+1 < LOCD) ? im[(y0+1)*LOCD + x0+1] : 0.0f;

    g_rot[idx] = v00*wy0*wx0 + v01*wy0*wx1 + v10*wy1*wx0 + v11*wy1*wx1;
}

// ---------------------------------------------------------------------------
// conv1 at t=0: p0 is a delta at (a=0, y=62, x=62) -> just stamp rot[0,b,0,f]
// ---------------------------------------------------------------------------
__global__ void conv1_t0_kernel()
{
    int idx = blockIdx.x * blockDim.x + threadIdx.x;
    if (idx >= BSZ*FCH*NPIX) return;
    int x  = idx % MAPD;
    int y  = (idx / MAPD) % MAPD;
    int f  = (idx / NPIX) % FCH;
    int b  = idx / (NPIX*FCH);
    float v = 0.0f;
    if (y >= 50 && y <= 74 && x >= 50 && x <= 74)
        v = g_rot[((b*NA + 0)*FCH + f)*KSZ + (y-50)*LOCD + (x-50)];
    g_oreg[idx] = v;
}

// ---------------------------------------------------------------------------
// conv1 (write-memory), t>=1:
// o_reg[b,f,y,x] = sum_{a,j,i} rot[t,b,a,f,j,i] * p[b,a,y+12-j,x+12-i]
// block = (ytile16, co-group of 8, b); 256 threads (2 warp-groups share tile+wts)
// Weights pre-duplicated in smem as [k][4 co-pair float4] for LDS.128 broadcast.
// ---------------------------------------------------------------------------
__global__ __launch_bounds__(256)
void conv1_kernel(int t, const float* __restrict__ psrc)
{
    extern __shared__ float smem[];
    float4* wtsv = (float4*)smem;                        // [KSZ][4] : (w,w,w',w')
    const ulonglong2* wtsu = (const ulonglong2*)smem;    // 1 ulonglong2 == 1 float4
    float2* pt2 = (float2*)(smem + WTS_BYTES/4);         // [TROWS][TC2] row-pairs
    const unsigned long long* pt64 = (const unsigned long long*)pt2;

    const int tid = threadIdx.x;
    const int wg  = tid >> 7;                    // warp-group 0/1
    const int wt  = tid & 127;
    const int yt  = blockIdx.x;
    const int cg  = blockIdx.y;                  // 0..3
    const int b   = blockIdx.z;
    const int y0  = yt * TYB;

    const float* rot_t = g_rot + t * (BSZ*NA*FCH*KSZ);

    unsigned long long acc[4][8];
#pragma unroll
    for (int s = 0; s < 4; s++)
#pragma unroll
        for (int co = 0; co < 8; co++) acc[s][co] = 0ULL;

    for (int a = 0; a < NA; a++) {
        __syncthreads();
        const float* ps = psrc + (b*NA + a)*NPIX;
        for (int i = tid; i < TROWS*TC2; i += 256) {
            int rr = i / TC2, cc = i % TC2;
            int gy = y0 + rr - 12, gx = cc - 12;
            float2 v;
            v.x = (gy   >= 0 && gy   < MAPD && gx >= 0 && gx < MAPD) ? ps[gy*MAPD + gx]     : 0.0f;
            v.y = (gy+1 >= 0 && gy+1 < MAPD && gx >= 0 && gx < MAPD) ? ps[(gy+1)*MAPD + gx] : 0.0f;
            pt2[i] = v;
        }
        // weights: transpose to [k][co-pair], duplicated
        const float* ws = rot_t + ((b*NA + a)*FCH + cg*8)*KSZ;
        for (int i = tid; i < KSZ*4; i += 256) {
            int k = i >> 2, cp = i & 3;
            float w0 = ws[(2*cp)*KSZ + k];
            float w1 = ws[(2*cp+1)*KSZ + k];
            wtsv[i] = make_float4(w0, w0, w1, w1);
        }
        __syncthreads();

        if (wt < MAPD) {
            for (int j = 0; j < LOCD; j++) {
                int kbase = j*LOCD;
                int pidx0 = (24 - j + wg*8)*TC2 + wt + 24;
#pragma unroll 5
                for (int i = 0; i < LOCD; i++) {
                    unsigned long long pv[4];
#pragma unroll
                    for (int s = 0; s < 4; s++)
                        pv[s] = pt64[pidx0 - i + s*(2*TC2)];
                    const ulonglong2* wv = wtsu + (kbase + i)*4;   // 4 float4 per k
                    ulonglong2 w01 = wv[0];
                    ulonglong2 w23 = wv[1];
#pragma unroll
                    for (int s = 0; s < 4; s++) {
                        FMA2(acc[s][0], pv[s], w01.x);
                        FMA2(acc[s][1], pv[s], w01.y);
                        FMA2(acc[s][2], pv[s], w23.x);
                        FMA2(acc[s][3], pv[s], w23.y);
                    }
                    ulonglong2 w45 = wv[2];
                    ulonglong2 w67 = wv[3];
#pragma unroll
                    for (int s = 0; s < 4; s++) {
                        FMA2(acc[s][4], pv[s], w45.x);
                        FMA2(acc[s][5], pv[s], w45.y);
                        FMA2(acc[s][6], pv[s], w67.x);
                        FMA2(acc[s][7], pv[s], w67.y);
                    }
                }
            }
        }
    }

    if (wt < MAPD) {
#pragma unroll
        for (int co = 0; co < 8; co++)
#pragma unroll
            for (int s = 0; s < 4; s++) {
                float lo, hi;
                UNPACK2(lo, hi, acc[s][co]);
                int y = y0 + wg*8 + 2*s;
                float* dst = g_oreg + (b*FCH + cg*8 + co)*NPIX + y*MAPD + wt;
                if (y   < MAPD) dst[0]    = lo;
                if (y+1 < MAPD) dst[MAPD] = hi;
            }
    }
}

// ---------------------------------------------------------------------------
// GRU cell per pixel + channel softmax.
// ---------------------------------------------------------------------------
__global__ __launch_bounds__(128)
void gru_kernel(const float* __restrict__ hprev,
                const float* __restrict__ w_ih, const float* __restrict__ w_hh,
                const float* __restrict__ b_ih, const float* __restrict__ b_hh,
                float* __restrict__ mout)
{
    __shared__ float4 s_wih[96*8];
    __shared__ float4 s_whh[96*8];
    __shared__ float  s_b[192];

    const int tid = threadIdx.x;
    const float4* wi4 = (const float4*)w_ih;
    const float4* wh4 = (const float4*)w_hh;
    for (int i = tid; i < 96*8; i += 128) { s_wih[i] = wi4[i]; s_whh[i] = wh4[i]; }
    if (tid < 96) { s_b[tid] = b_ih[tid]; s_b[96+tid] = b_hh[tid]; }
    __syncthreads();

    const int pix = blockIdx.x * 128 + tid;
    if (pix >= NPIX) return;
    const int b = blockIdx.y;

    float x[32], h[32];
#pragma unroll
    for (int c = 0; c < 32; c++) {
        x[c] = g_oreg[(b*FCH + c)*NPIX + pix];
        h[c] = hprev[(b*FCH + c)*NPIX + pix];
    }

    float mx = -1e30f;
    float mvals[32];
    for (int c = 0; c < 32; c++) {
        float accr = s_b[c]      + s_b[96+c];
        float accz = s_b[32+c]   + s_b[128+c];
        float acci = s_b[64+c];
        float acch = s_b[160+c];
        const float4* wr_i = s_wih + c*8;
        const float4* wz_i = s_wih + (32+c)*8;
        const float4* wn_i = s_wih + (64+c)*8;
        const float4* wr_h = s_whh + c*8;
        const float4* wz_h = s_whh + (32+c)*8;
        const float4* wn_h = s_whh + (64+c)*8;
#pragma unroll
        for (int k = 0; k < 8; k++) {
            float4 wv;
            wv = wr_i[k]; accr += wv.x*x[4*k] + wv.y*x[4*k+1] + wv.z*x[4*k+2] + wv.w*x[4*k+3];
            wv = wr_h[k]; accr += wv.x*h[4*k] + wv.y*h[4*k+1] + wv.z*h[4*k+2] + wv.w*h[4*k+3];
            wv = wz_i[k]; accz += wv.x*x[4*k] + wv.y*x[4*k+1] + wv.z*x[4*k+2] + wv.w*x[4*k+3];
            wv = wz_h[k]; accz += wv.x*h[4*k] + wv.y*h[4*k+1] + wv.z*h[4*k+2] + wv.w*h[4*k+3];
            wv = wn_i[k]; acci += wv.x*x[4*k] + wv.y*x[4*k+1] + wv.z*x[4*k+2] + wv.w*x[4*k+3];
            wv = wn_h[k]; acch += wv.x*h[4*k] + wv.y*h[4*k+1] + wv.z*h[4*k+2] + wv.w*h[4*k+3];
        }
        float r = 1.0f/(1.0f + expf(-accr));
        float z = 1.0f/(1.0f + expf(-accz));
        float n = tanhf(acci + r*acch);
        float mv = (1.0f - z)*n + z*h[c];
        mvals[c] = mv;
        mout[(b*FCH + c)*NPIX + pix] = mv;
        mx = fmaxf(mx, mv);
    }

    float sum = 0.0f;
    float e[32];
#pragma unroll
    for (int c = 0; c < 32; c++) { e[c] = expf(mvals[c] - mx); sum += e[c]; }
    float inv = 1.0f / sum;
#pragma unroll
    for (int c = 1; c < 32; c++)
        g_msm[(b*(FCH-1) + (c-1))*NPIX + pix] = e[c] * inv;
}

// ---------------------------------------------------------------------------
// conv2 (localize): scores[b,a,y,x] = sum_{c,ky,kx}
//    msm[b,c,y+ky-12,x+kx-12] * rot[t+1,b,a,c+1,ky,kx]
// block = (ytile16, channel-split q, b); 256 threads; predup weights
// ---------------------------------------------------------------------------
__global__ __launch_bounds__(256)
void conv2_kernel(int t)
{
    extern __shared__ float smem[];
    float4* wtsv = (float4*)smem;
    const ulonglong2* wtsu = (const ulonglong2*)smem;
    float2* pt2 = (float2*)(smem + WTS_BYTES/4);
    const unsigned long long* pt64 = (const unsigned long long*)pt2;

    const int tid = threadIdx.x;
    const int wg  = tid >> 7;
    const int wt  = tid & 127;
    const int yt  = blockIdx.x;
    const int q   = blockIdx.y;                  // 0..3
    const int b   = blockIdx.z;
    const int y0  = yt * TYB;
    const int c0  = q * 8;
    int c1 = c0 + 8;
    if (c1 > FCH-1) c1 = FCH-1;

    const float* rot_n = g_rot + (t+1) * (BSZ*NA*FCH*KSZ);

    unsigned long long acc[4][8];
#pragma unroll
    for (int s = 0; s < 4; s++)
#pragma unroll
        for (int a = 0; a < 8; a++) acc[s][a] = 0ULL;

    for (int c = c0; c < c1; c++) {
        __syncthreads();
        const float* ps = g_msm + (b*(FCH-1) + c)*NPIX;
        for (int i = tid; i < TROWS*TC2; i += 256) {
            int rr = i / TC2, cc = i % TC2;
            int gy = y0 + rr - 12, gx = cc - 12;
            float2 v;
            v.x = (gy   >= 0 && gy   < MAPD && gx >= 0 && gx < MAPD) ? ps[gy*MAPD + gx]     : 0.0f;
            v.y = (gy+1 >= 0 && gy+1 < MAPD && gx >= 0 && gx < MAPD) ? ps[(gy+1)*MAPD + gx] : 0.0f;
            pt2[i] = v;
        }
        // weights: angle a plays the "co" role; transpose to [k][a-pair], dup
        const float* wbase = rot_n + (b*NA*FCH + (c+1))*KSZ;
        for (int i = tid; i < KSZ*4; i += 256) {
            int k = i >> 2, ap = i & 3;
            float w0 = wbase[(2*ap)*FCH*KSZ + k];
            float w1 = wbase[(2*ap+1)*FCH*KSZ + k];
            wtsv[i] = make_float4(w0, w0, w1, w1);
        }
        __syncthreads();

        if (wt < MAPD) {
            for (int ky = 0; ky < LOCD; ky++) {
                int kbase = ky*LOCD;
                int pidx0 = (ky + wg*8)*TC2 + wt;
#pragma unroll 5
                for (int kx = 0; kx < LOCD; kx++) {
                    unsigned long long pv[4];
#pragma unroll
                    for (int s = 0; s < 4; s++)
                        pv[s] = pt64[pidx0 + kx + s*(2*TC2)];
                    const ulonglong2* wv = wtsu + (kbase + kx)*4;   // 4 float4 per k
                    ulonglong2 w01 = wv[0];
                    ulonglong2 w23 = wv[1];
#pragma unroll
                    for (int s = 0; s < 4; s++) {
                        FMA2(acc[s][0], pv[s], w01.x);
                        FMA2(acc[s][1], pv[s], w01.y);
                        FMA2(acc[s][2], pv[s], w23.x);
                        FMA2(acc[s][3], pv[s], w23.y);
                    }
                    ulonglong2 w45 = wv[2];
                    ulonglong2 w67 = wv[3];
#pragma unroll
                    for (int s = 0; s < 4; s++) {
                        FMA2(acc[s][4], pv[s], w45.x);
                        FMA2(acc[s][5], pv[s], w45.y);
                        FMA2(acc[s][6], pv[s], w67.x);
                        FMA2(acc[s][7], pv[s], w67.y);
                    }
                }
            }
        }
    }

    if (wt < MAPD) {
#pragma unroll
        for (int a = 0; a < 8; a++)
#pragma unroll
            for (int s = 0; s < 4; s++) {
                float lo, hi;
                UNPACK2(lo, hi, acc[s][a]);
                int y = y0 + wg*8 + 2*s;
                float* dst = g_scoresP[q] + (b*NA + a)*NPIX + y*MAPD + wt;
                if (y   < MAPD) dst[0]    = lo;
                if (y+1 < MAPD) dst[MAPD] = hi;
            }
    }
}

// ---------------------------------------------------------------------------
// Global softmax over (A,H,W), summing the 4 conv2 partials.
// ---------------------------------------------------------------------------
__global__ void softmax_pose_kernel(float* __restrict__ pdst)
{
    const int b = blockIdx.x;
    const int base = b*NA*NPIX;
    float* o = pdst + base;
    const int N = NA*NPIX;
    __shared__ float red[33];
    const int tid = threadIdx.x;

    float mx = -1e30f;
    for (int i = tid; i < N; i += 1024) {
        float s = g_scoresP[0][base+i] + g_scoresP[1][base+i]
                + g_scoresP[2][base+i] + g_scoresP[3][base+i];
        mx = fmaxf(mx, s);
    }
#pragma unroll
    for (int off = 16; off; off >>= 1) mx = fmaxf(mx, __shfl_xor_sync(0xffffffffu, mx, off));
    if ((tid & 31) == 0) red[tid >> 5] = mx;
    __syncthreads();
    if (tid < 32) {
        float v = red[tid];
#pragma unroll
        for (int off = 16; off; off >>= 1) v = fmaxf(v, __shfl_xor_sync(0xffffffffu, v, off));
        if (tid == 0) red[32] = v;
    }
    __syncthreads();
    mx = red[32];
    __syncthreads();

    float sum = 0.0f;
    for (int i = tid; i < N; i += 1024) {
        float s = g_scoresP[0][base+i] + g_scoresP[1][base+i]
                + g_scoresP[2][base+i] + g_scoresP[3][base+i];
        sum += expf(s - mx);
    }
#pragma unroll
    for (int off = 16; off; off >>= 1) sum += __shfl_xor_sync(0xffffffffu, sum, off);
    if ((tid & 31) == 0) red[tid >> 5] = sum;
    __syncthreads();
    if (tid < 32) {
        float v = red[tid];
#pragma unroll
        for (int off = 16; off; off >>= 1) v += __shfl_xor_sync(0xffffffffu, v, off);
        if (tid == 0) red[32] = v;
    }
    __syncthreads();
    float inv = 1.0f / red[32];

    for (int i = tid; i < N; i += 1024) {
        float s = g_scoresP[0][base+i] + g_scoresP[1][base+i]
                + g_scoresP[2][base+i] + g_scoresP[3][base+i];
        o[i] = expf(s - mx) * inv;
    }
}

// ---------------------------------------------------------------------------
// Host launcher (graph-capturable, allocation-free).
// Output: poses_all (5,8,8,125,125) | maps_all (5,8,32,125,125) | m_final (8,32,125,125)
// ---------------------------------------------------------------------------
extern "C" void kernel_launch(void* const* d_in, const int* in_sizes, int n_in,
                              void* d_out, int out_size)
{
    const float* img   = (const float*)d_in[0];
    const float* maps0 = (const float*)d_in[1];
    const float* w_ih  = (const float*)d_in[3];
    const float* w_hh  = (const float*)d_in[4];
    const float* b_ih  = (const float*)d_in[5];
    const float* b_hh  = (const float*)d_in[6];

    float* out   = (float*)d_out;
    float* poses = out;
    float* mapso = out + 5*BSZ*NA*NPIX;
    float* mfin  = out + 5*BSZ*NA*NPIX + 5*BSZ*FCH*NPIX;

    cudaFuncSetAttribute(conv1_kernel, cudaFuncAttributeMaxDynamicSharedMemorySize, CONV_SMEM);
    cudaFuncSetAttribute(conv2_kernel, cudaFuncAttributeMaxDynamicSharedMemorySize, CONV_SMEM);

    resample_kernel<<<(LL*BSZ*NA*FCH*KSZ + 255)/256, 256>>>(img);

    for (int t = 0; t < LL-1; t++) {
        const float* hsrc = (t == 0) ? maps0 : (mapso + (t-1)*BSZ*FCH*NPIX);
        float* mdst = mapso + t*BSZ*FCH*NPIX;
        float* pdst = poses + t*BSZ*NA*NPIX;

        if (t == 0) {
            conv1_t0_kernel<<<(BSZ*FCH*NPIX + 255)/256, 256>>>();
        } else {
            const float* psrc = poses + (t-1)*BSZ*NA*NPIX;
            conv1_kernel<<<dim3(NYT, 4, BSZ), 256, CONV_SMEM>>>(t, psrc);
        }
        gru_kernel<<<dim3((NPIX + 127)/128, BSZ), 128>>>(hsrc, w_ih, w_hh, b_ih, b_hh, mdst);
        conv2_kernel<<<dim3(NYT, 4, BSZ), 256, CONV_SMEM>>>(t);
        softmax_pose_kernel<<<BSZ, 1024>>>(pdst);
    }

    cudaMemcpyAsync(mfin, mapso + 4*BSZ*FCH*NPIX,
                    (size_t)BSZ*FCH*NPIX*sizeof(float),
                    cudaMemcpyDeviceToDevice);
}

// round 8
// speedup vs baseline: 1.1065x; 1.1053x over previous
#include <cuda_runtime.h>
#include <cuda_bf16.h>
#include <math.h>
#include <stdint.h>

// Problem constants
#define LL    6
#define BSZ   8
#define FCH   32
#define MAPD  125
#define LOCD  25
#define NA    8
#define NPIX  (MAPD*MAPD)   // 15625
#define KSZ   (LOCD*LOCD)   // 625
#define ROTCH (BSZ*NA*FCH*KSZ)

// Tensor-conv tiling
#define RY    4             // output rows per block
#define NYG   32            // ceil(125/4)
#define AROWS 28            // RY + 24 halo
#define TAW   160           // padded row width (elements), e = gx + 12, e in [0,160)
#define NBW   3200          // B words per half: 25ky * 2kxh * 8j * 8n
#define SMEMSZ (4*AROWS*TAW*2 + 2*NBW*4)   // 35840 + 25600 = 61440

// Scratch (device globals; no allocation allowed)
__device__ float g_rot[LL*ROTCH];            // rotated tiles [l][b][a][f][25][25]
__device__ float g_oreg[BSZ*FCH*NPIX];       // conv1 output (GRU input)
__device__ float g_msm[BSZ*(FCH-1)*NPIX];    // channel-softmaxed maps, ch 1..31
__device__ float g_scores[BSZ*NA*NPIX];      // conv2 output (pre-softmax)

// ---------------------------------------------------------------------------
// bf16 helpers
// ---------------------------------------------------------------------------
__device__ __forceinline__ void split2(float v, unsigned short& h, unsigned short& l)
{
    __nv_bfloat16 hb = __float2bfloat16_rn(v);
    h = *reinterpret_cast<unsigned short*>(&hb);
    float r = v - __bfloat162float(hb);
    __nv_bfloat16 lb = __float2bfloat16_rn(r);
    l = *reinterpret_cast<unsigned short*>(&lb);
}

__device__ __forceinline__ void mma_bf16(float* d,
    uint32_t a0, uint32_t a1, uint32_t a2, uint32_t a3, uint32_t b0, uint32_t b1)
{
    asm volatile(
        "mma.sync.aligned.m16n8k16.row.col.f32.bf16.bf16.f32 "
        "{%0,%1,%2,%3}, {%4,%5,%6,%7}, {%8,%9}, {%0,%1,%2,%3};\n"
        : "+f"(d[0]), "+f"(d[1]), "+f"(d[2]), "+f"(d[3])
        : "r"(a0), "r"(a1), "r"(a2), "r"(a3), "r"(b0), "r"(b1));
}

// ---------------------------------------------------------------------------
// Rotation resample: image_cls (L,BS,F,25,25) -> g_rot (L,BS,A,F,25,25)
// ---------------------------------------------------------------------------
__global__ void resample_kernel(const float* __restrict__ img)
{
    int idx = blockIdx.x * blockDim.x + threadIdx.x;
    const int total = LL*ROTCH;
    if (idx >= total) return;

    int xx = idx % LOCD;
    int yy = (idx / LOCD) % LOCD;
    int f  = (idx / KSZ) % FCH;
    int a  = (idx / (KSZ*FCH)) % NA;
    int lb = idx / (KSZ*FCH*NA);

    float gx = -1.0f + (float)xx * (2.0f/24.0f);
    float gy = -1.0f + (float)yy * (2.0f/24.0f);
    float ang = (float)a * 0.78539816339744830961f;
    float sn, c;
    sincosf(ang, &sn, &c);
    float px = (c*gx - sn*gy + 1.0f) * 12.0f;
    float py = (sn*gx + c*gy + 1.0f) * 12.0f;

    int x0 = (int)floorf(px);
    int y0 = (int)floorf(py);
    float wx1 = px - (float)x0, wy1 = py - (float)y0;
    float wx0 = 1.0f - wx1,     wy0 = 1.0f - wy1;

    const float* im = img + (lb*FCH + f)*KSZ;
    float v00 = (y0   >= 0 && y0   < LOCD && x0   >= 0 && x0   < LOCD) ? im[y0*LOCD + x0]       : 0.0f;
    float v01 = (y0   >= 0 && y0   < LOCD && x0+1 >= 0 && x0+1 < LOCD) ? im[y0*LOCD + x0+1]     : 0.0f;
    float v10 = (y0+1 >= 0 && y0+1 < LOCD && x0   >= 0 && x0   < LOCD) ? im[(y0+1)*LOCD + x0]   : 0.0f;
    float v11 = (y0+1 >= 0 && y0+1 < LOCD && x0+1 >= 0 && x0+1 < LOCD) ? im[(y0+1)*LOCD + x0+1] : 0.0f;

    g_rot[idx] = v00*wy0*wx0 + v01*wy0*wx1 + v10*wy1*wx0 + v11*wy1*wx1;
}

// ---------------------------------------------------------------------------
// conv1 at t=0: p0 is a delta at (a=0, y=62, x=62) -> stamp rot[0,b,0,f]
// ---------------------------------------------------------------------------
__global__ void conv1_t0_kernel()
{
    int idx = blockIdx.x * blockDim.x + threadIdx.x;
    if (idx >= BSZ*FCH*NPIX) return;
    int x  = idx % MAPD;
    int y  = (idx / MAPD) % MAPD;
    int f  = (idx / NPIX) % FCH;
    int b  = idx / (NPIX*FCH);
    float v = 0.0f;
    if (y >= 50 && y <= 74 && x >= 50 && x <= 74)
        v = g_rot[((b*NA + 0)*FCH + f)*KSZ + (y-50)*LOCD + (x-50)];
    g_oreg[idx] = v;
}

// ---------------------------------------------------------------------------
// Unified tensor-core correlation kernel (bf16 hi/lo split, mma.sync m16n8k16).
//
// out[b, fg*8+n, y, x] = sum_{ci, ky, kx} plane[b,ci, y-12+ky, x-12+kx] * W
//   mode 0 (conv2): plane = msm (31 ch), W = wts[((b*8+n)*32 + ci+1)*625 + ky*25+kx]
//   mode 1 (conv1): plane = poses (8 ch), W = wts[((b*8+ci)*32 + fg*8+n)*625 + (24-ky)*25+(24-kx)]
//
// Block: (y-group of 4 rows, fg, b); 256 threads = 8 warps; warp w -> x-tile 16w.
// A tiles in smem as bf16 hi/lo with even/odd parity copies (aligned LDS.32).
// Toeplitz A: fragment regs a1 == a2, so only 3 loads per fragment.
// ---------------------------------------------------------------------------
__global__ __launch_bounds__(256, 2)
void convmma_kernel(const float* __restrict__ planes, int nplanes,
                    const float* __restrict__ wts,
                    int mode, int OC,
                    float* __restrict__ outp)
{
    extern __shared__ char sm[];
    unsigned short* AhiE = (unsigned short*)sm;          // [AROWS*TAW]
    unsigned short* AhiO = AhiE + AROWS*TAW;
    unsigned short* AloE = AhiO + AROWS*TAW;
    unsigned short* AloO = AloE + AROWS*TAW;
    uint32_t* Bhi = (uint32_t*)(sm + 4*AROWS*TAW*2);     // [NBW]
    uint32_t* Blo = Bhi + NBW;
    const uint32_t* AhiE32 = (const uint32_t*)AhiE;
    const uint32_t* AhiO32 = (const uint32_t*)AhiO;
    const uint32_t* AloE32 = (const uint32_t*)AloE;
    const uint32_t* AloO32 = (const uint32_t*)AloO;

    const int tid  = threadIdx.x;
    const int warp = tid >> 5;
    const int lane = tid & 31;
    const int g    = lane >> 2;          // group id
    const int q    = lane & 3;           // thread-in-group
    const int x0   = warp * 16;          // M-tile base
    const int yg   = blockIdx.x;
    const int fg   = blockIdx.y;
    const int b    = blockIdx.z;
    const int y0   = yg * RY;
    const int pbase = x0 + g + 2*q;      // Toeplitz element base (k offset added later)

    float acc[RY][4];
#pragma unroll
    for (int y = 0; y < RY; y++)
#pragma unroll
        for (int i = 0; i < 4; i++) acc[y][i] = 0.0f;

    for (int ci = 0; ci < nplanes; ci++) {
        __syncthreads();   // previous iteration's smem reads complete

        // ---- A fill: rows y0-12 .. y0+15, elements e=gx+12 in [0,160) ----
        const float* src = planes + (b*nplanes + ci)*NPIX;
        for (int idx = tid; idx < AROWS*TAW; idx += 256) {
            int r = idx / TAW, e = idx - r*TAW;
            int gy = y0 - 12 + r, gx = e - 12;
            float v = (gy >= 0 && gy < MAPD && gx >= 0 && gx < MAPD)
                      ? src[gy*MAPD + gx] : 0.0f;
            unsigned short h, l;
            split2(v, h, l);
            AhiE[idx] = h; AloE[idx] = l;
            if (e > 0) { AhiO[idx-1] = h; AloO[idx-1] = l; }
        }

        // ---- B fill: word [ky][kxh][j][n] = (w(kx0), w(kx0+1)) bf16 pair ----
        for (int i = tid; i < NBW; i += 256) {
            int n   = i & 7;
            int j   = (i >> 3) & 7;
            int kxh = (i >> 6) & 1;
            int ky  = i >> 7;
            int kx0 = kxh*16 + 2*j;
            float w0 = 0.0f, w1 = 0.0f;
            if (mode == 0) {
                const float* wb = wts + ((b*NA + n)*FCH + (ci+1))*KSZ + ky*LOCD;
                if (kx0   < LOCD) w0 = wb[kx0];
                if (kx0+1 < LOCD) w1 = wb[kx0+1];
            } else {
                const float* wb = wts + ((b*NA + ci)*FCH + (fg*8 + n))*KSZ + (24-ky)*LOCD;
                if (kx0   < LOCD) w0 = wb[24-kx0];
                if (kx0+1 < LOCD) w1 = wb[24-(kx0+1)];
            }
            unsigned short h0, l0, h1, l1;
            split2(w0, h0, l0);
            split2(w1, h1, l1);
            Bhi[i] = (uint32_t)h0 | ((uint32_t)h1 << 16);
            Blo[i] = (uint32_t)l0 | ((uint32_t)l1 << 16);
        }
        __syncthreads();

        // ---- MMA loop ----
        for (int ky = 0; ky < LOCD; ky++) {
#pragma unroll
            for (int kxh = 0; kxh < 2; kxh++) {
                int bb = (ky*2 + kxh)*64;
                uint32_t bh0 = Bhi[bb + q*8 + g];
                uint32_t bh1 = Bhi[bb + (q+4)*8 + g];
                uint32_t bl0 = Blo[bb + q*8 + g];
                uint32_t bl1 = Blo[bb + (q+4)*8 + g];

                int p = pbase + (kxh << 4);
                const uint32_t* Ah = (p & 1) ? AhiO32 : AhiE32;
                const uint32_t* Al = (p & 1) ? AloO32 : AloE32;
                int wo = p >> 1;
#pragma unroll
                for (int y = 0; y < RY; y++) {
                    int off = (y + ky)*(TAW/2) + wo;
                    uint32_t a0 = Ah[off], a1 = Ah[off+4], a3 = Ah[off+8];
                    uint32_t l0 = Al[off], l1 = Al[off+4], l3 = Al[off+8];
                    mma_bf16(acc[y], a0, a1, a1, a3, bh0, bh1);   // hi*hi
                    mma_bf16(acc[y], a0, a1, a1, a3, bl0, bl1);   // hi*lo
                    mma_bf16(acc[y], l0, l1, l1, l3, bh0, bh1);   // lo*hi
                }
            }
        }
    }

    // ---- epilogue: D rows g/g+8, cols 2q/2q+1 ----
#pragma unroll
    for (int y = 0; y < RY; y++) {
        int gy = y0 + y;
        if (gy >= MAPD) continue;
        float* ob = outp + (b*OC + fg*8)*NPIX + gy*MAPD;
        int n0 = 2*q;
        int x1 = x0 + g;
        ob[n0*NPIX + x1]     = acc[y][0];
        ob[(n0+1)*NPIX + x1] = acc[y][1];
        int x2 = x1 + 8;
        if (x2 < MAPD) {
            ob[n0*NPIX + x2]     = acc[y][2];
            ob[(n0+1)*NPIX + x2] = acc[y][3];
        }
    }
}

// ---------------------------------------------------------------------------
// GRU cell per pixel + channel softmax.
// ---------------------------------------------------------------------------
__global__ __launch_bounds__(128)
void gru_kernel(const float* __restrict__ hprev,
                const float* __restrict__ w_ih, const float* __restrict__ w_hh,
                const float* __restrict__ b_ih, const float* __restrict__ b_hh,
                float* __restrict__ mout)
{
    __shared__ float4 s_wih[96*8];
    __shared__ float4 s_whh[96*8];
    __shared__ float  s_b[192];

    const int tid = threadIdx.x;
    const float4* wi4 = (const float4*)w_ih;
    const float4* wh4 = (const float4*)w_hh;
    for (int i = tid; i < 96*8; i += 128) { s_wih[i] = wi4[i]; s_whh[i] = wh4[i]; }
    if (tid < 96) { s_b[tid] = b_ih[tid]; s_b[96+tid] = b_hh[tid]; }
    __syncthreads();

    const int pix = blockIdx.x * 128 + tid;
    if (pix >= NPIX) return;
    const int b = blockIdx.y;

    float x[32], h[32];
#pragma unroll
    for (int c = 0; c < 32; c++) {
        x[c] = g_oreg[(b*FCH + c)*NPIX + pix];
        h[c] = hprev[(b*FCH + c)*NPIX + pix];
    }

    float mx = -1e30f;
    float mvals[32];
    for (int c = 0; c < 32; c++) {
        float accr = s_b[c]      + s_b[96+c];
        float accz = s_b[32+c]   + s_b[128+c];
        float acci = s_b[64+c];
        float acch = s_b[160+c];
        const float4* wr_i = s_wih + c*8;
        const float4* wz_i = s_wih + (32+c)*8;
        const float4* wn_i = s_wih + (64+c)*8;
        const float4* wr_h = s_whh + c*8;
        const float4* wz_h = s_whh + (32+c)*8;
        const float4* wn_h = s_whh + (64+c)*8;
#pragma unroll
        for (int k = 0; k < 8; k++) {
            float4 wv;
            wv = wr_i[k]; accr += wv.x*x[4*k] + wv.y*x[4*k+1] + wv.z*x[4*k+2] + wv.w*x[4*k+3];
            wv = wr_h[k]; accr += wv.x*h[4*k] + wv.y*h[4*k+1] + wv.z*h[4*k+2] + wv.w*h[4*k+3];
            wv = wz_i[k]; accz += wv.x*x[4*k] + wv.y*x[4*k+1] + wv.z*x[4*k+2] + wv.w*x[4*k+3];
            wv = wz_h[k]; accz += wv.x*h[4*k] + wv.y*h[4*k+1] + wv.z*h[4*k+2] + wv.w*h[4*k+3];
            wv = wn_i[k]; acci += wv.x*x[4*k] + wv.y*x[4*k+1] + wv.z*x[4*k+2] + wv.w*x[4*k+3];
            wv = wn_h[k]; acch += wv.x*h[4*k] + wv.y*h[4*k+1] + wv.z*h[4*k+2] + wv.w*h[4*k+3];
        }
        float r = 1.0f/(1.0f + expf(-accr));
        float z = 1.0f/(1.0f + expf(-accz));
        float n = tanhf(acci + r*acch);
        float mv = (1.0f - z)*n + z*h[c];
        mvals[c] = mv;
        mout[(b*FCH + c)*NPIX + pix] = mv;
        mx = fmaxf(mx, mv);
    }

    float sum = 0.0f;
    float e[32];
#pragma unroll
    for (int c = 0; c < 32; c++) { e[c] = expf(mvals[c] - mx); sum += e[c]; }
    float inv = 1.0f / sum;
#pragma unroll
    for (int c = 1; c < 32; c++)
        g_msm[(b*(FCH-1) + (c-1))*NPIX + pix] = e[c] * inv;
}

// ---------------------------------------------------------------------------
// Global softmax over (A,H,W) from g_scores.
// ---------------------------------------------------------------------------
__global__ void softmax_pose_kernel(float* __restrict__ pdst)
{
    const int b = blockIdx.x;
    const float* s = g_scores + b*NA*NPIX;
    float* o = pdst + b*NA*NPIX;
    const int N = NA*NPIX;
    __shared__ float red[33];
    const int tid = threadIdx.x;

    float mx = -1e30f;
    for (int i = tid; i < N; i += 1024) mx = fmaxf(mx, s[i]);
#pragma unroll
    for (int off = 16; off; off >>= 1) mx = fmaxf(mx, __shfl_xor_sync(0xffffffffu, mx, off));
    if ((tid & 31) == 0) red[tid >> 5] = mx;
    __syncthreads();
    if (tid < 32) {
        float v = red[tid];
#pragma unroll
        for (int off = 16; off; off >>= 1) v = fmaxf(v, __shfl_xor_sync(0xffffffffu, v, off));
        if (tid == 0) red[32] = v;
    }
    __syncthreads();
    mx = red[32];
    __syncthreads();

    float sum = 0.0f;
    for (int i = tid; i < N; i += 1024) sum += expf(s[i] - mx);
#pragma unroll
    for (int off = 16; off; off >>= 1) sum += __shfl_xor_sync(0xffffffffu, sum, off);
    if ((tid & 31) == 0) red[tid >> 5] = sum;
    __syncthreads();
    if (tid < 32) {
        float v = red[tid];
#pragma unroll
        for (int off = 16; off; off >>= 1) v += __shfl_xor_sync(0xffffffffu, v, off);
        if (tid == 0) red[32] = v;
    }
    __syncthreads();
    float inv = 1.0f / red[32];

    for (int i = tid; i < N; i += 1024) o[i] = expf(s[i] - mx) * inv;
}

// ---------------------------------------------------------------------------
// Host launcher (graph-capturable, allocation-free).
// Output: poses_all (5,8,8,125,125) | maps_all (5,8,32,125,125) | m_final (8,32,125,125)
// ---------------------------------------------------------------------------
extern "C" void kernel_launch(void* const* d_in, const int* in_sizes, int n_in,
                              void* d_out, int out_size)
{
    const float* img   = (const float*)d_in[0];
    const float* maps0 = (const float*)d_in[1];
    const float* w_ih  = (const float*)d_in[3];
    const float* w_hh  = (const float*)d_in[4];
    const float* b_ih  = (const float*)d_in[5];
    const float* b_hh  = (const float*)d_in[6];

    float* out   = (float*)d_out;
    float* poses = out;
    float* mapso = out + 5*BSZ*NA*NPIX;
    float* mfin  = out + 5*BSZ*NA*NPIX + 5*BSZ*FCH*NPIX;

    float *d_rot, *d_msm, *d_oreg, *d_scores;
    cudaGetSymbolAddress((void**)&d_rot,    g_rot);
    cudaGetSymbolAddress((void**)&d_msm,    g_msm);
    cudaGetSymbolAddress((void**)&d_oreg,   g_oreg);
    cudaGetSymbolAddress((void**)&d_scores, g_scores);

    cudaFuncSetAttribute(convmma_kernel, cudaFuncAttributeMaxDynamicSharedMemorySize, SMEMSZ);

    resample_kernel<<<(LL*ROTCH + 255)/256, 256>>>(img);

    for (int t = 0; t < LL-1; t++) {
        const float* hsrc = (t == 0) ? maps0 : (mapso + (t-1)*BSZ*FCH*NPIX);
        float* mdst = mapso + t*BSZ*FCH*NPIX;
        float* pdst = poses + t*BSZ*NA*NPIX;

        if (t == 0) {
            conv1_t0_kernel<<<(BSZ*FCH*NPIX + 255)/256, 256>>>();
        } else {
            const float* psrc = poses + (t-1)*BSZ*NA*NPIX;
            convmma_kernel<<<dim3(NYG, 4, BSZ), 256, SMEMSZ>>>(
                psrc, NA, d_rot + (size_t)t*ROTCH, 1, FCH, d_oreg);
        }
        gru_kernel<<<dim3((NPIX + 127)/128, BSZ), 128>>>(hsrc, w_ih, w_hh, b_ih, b_hh, mdst);
        convmma_kernel<<<dim3(NYG, 1, BSZ), 256, SMEMSZ>>>(
            d_msm, FCH-1, d_rot + (size_t)(t+1)*ROTCH, 0, NA, d_scores);
        softmax_pose_kernel<<<BSZ, 1024>>>(pdst);
    }

    cudaMemcpyAsync(mfin, mapso + 4*BSZ*FCH*NPIX,
                    (size_t)BSZ*FCH*NPIX*sizeof(float),
                    cudaMemcpyDeviceToDevice);
}

// round 9
// speedup vs baseline: 1.8471x; 1.6693x over previous
#include <cuda_runtime.h>
#include <cuda_bf16.h>
#include <math.h>
#include <stdint.h>

// Problem constants
#define LL    6
#define BSZ   8
#define FCH   32
#define MAPD  125
#define LOCD  25
#define NA    8
#define NPIX  (MAPD*MAPD)   // 15625
#define KSZ   (LOCD*LOCD)   // 625
#define ROTCH (BSZ*NA*FCH*KSZ)

// Tensor-conv tiling
#define RY    4             // output rows per block
#define NYG   32            // ceil(125/4)
#define AROWS 28            // RY + 24 halo
#define TAW   160           // padded row width (elements), e = gx + 12
#define NB2   1600          // uint2 B entries per half: 25ky * 2kxh * 8g * 4q
#define SMEMSZ (4*AROWS*TAW*2 + 2*NB2*8)   // 35840 + 25600 = 61440

// Scratch (device globals; no allocation allowed)
__device__ float g_rot[LL*ROTCH];            // rotated tiles [l][b][a][f][25][25]
__device__ float g_oreg[BSZ*FCH*NPIX];       // conv1 output (GRU input)
__device__ float g_msm[BSZ*(FCH-1)*NPIX];    // channel-softmaxed maps, ch 1..31
__device__ float g_scores[BSZ*NA*NPIX];      // conv2 output (pre-softmax)

// ---------------------------------------------------------------------------
// bf16 helpers
// ---------------------------------------------------------------------------
__device__ __forceinline__ void split2(float v, unsigned short& h, unsigned short& l)
{
    __nv_bfloat16 hb = __float2bfloat16_rn(v);
    h = *reinterpret_cast<unsigned short*>(&hb);
    float r = v - __bfloat162float(hb);
    __nv_bfloat16 lb = __float2bfloat16_rn(r);
    l = *reinterpret_cast<unsigned short*>(&lb);
}

__device__ __forceinline__ void mma_bf16(float* d,
    uint32_t a0, uint32_t a1, uint32_t a2, uint32_t a3, uint32_t b0, uint32_t b1)
{
    asm volatile(
        "mma.sync.aligned.m16n8k16.row.col.f32.bf16.bf16.f32 "
        "{%0,%1,%2,%3}, {%4,%5,%6,%7}, {%8,%9}, {%0,%1,%2,%3};\n"
        : "+f"(d[0]), "+f"(d[1]), "+f"(d[2]), "+f"(d[3])
        : "r"(a0), "r"(a1), "r"(a2), "r"(a3), "r"(b0), "r"(b1));
}

// ---------------------------------------------------------------------------
// Rotation resample: image_cls (L,BS,F,25,25) -> g_rot (L,BS,A,F,25,25)
// ---------------------------------------------------------------------------
__global__ void resample_kernel(const float* __restrict__ img)
{
    int idx = blockIdx.x * blockDim.x + threadIdx.x;
    const int total = LL*ROTCH;
    if (idx >= total) return;

    int xx = idx % LOCD;
    int yy = (idx / LOCD) % LOCD;
    int f  = (idx / KSZ) % FCH;
    int a  = (idx / (KSZ*FCH)) % NA;
    int lb = idx / (KSZ*FCH*NA);

    float gx = -1.0f + (float)xx * (2.0f/24.0f);
    float gy = -1.0f + (float)yy * (2.0f/24.0f);
    float ang = (float)a * 0.78539816339744830961f;
    float sn, c;
    sincosf(ang, &sn, &c);
    float px = (c*gx - sn*gy + 1.0f) * 12.0f;
    float py = (sn*gx + c*gy + 1.0f) * 12.0f;

    int x0 = (int)floorf(px);
    int y0 = (int)floorf(py);
    float wx1 = px - (float)x0, wy1 = py - (float)y0;
    float wx0 = 1.0f - wx1,     wy0 = 1.0f - wy1;

    const float* im = img + (lb*FCH + f)*KSZ;
    float v00 = (y0   >= 0 && y0   < LOCD && x0   >= 0 && x0   < LOCD) ? im[y0*LOCD + x0]       : 0.0f;
    float v01 = (y0   >= 0 && y0   < LOCD && x0+1 >= 0 && x0+1 < LOCD) ? im[y0*LOCD + x0+1]     : 0.0f;
    float v10 = (y0+1 >= 0 && y0+1 < LOCD && x0   >= 0 && x0   < LOCD) ? im[(y0+1)*LOCD + x0]   : 0.0f;
    float v11 = (y0+1 >= 0 && y0+1 < LOCD && x0+1 >= 0 && x0+1 < LOCD) ? im[(y0+1)*LOCD + x0+1] : 0.0f;

    g_rot[idx] = v00*wy0*wx0 + v01*wy0*wx1 + v10*wy1*wx0 + v11*wy1*wx1;
}

// ---------------------------------------------------------------------------
// conv1 at t=0: p0 is a delta at (a=0, y=62, x=62) -> stamp rot[0,b,0,f]
// ---------------------------------------------------------------------------
__global__ void conv1_t0_kernel()
{
    int idx = blockIdx.x * blockDim.x + threadIdx.x;
    if (idx >= BSZ*FCH*NPIX) return;
    int x  = idx % MAPD;
    int y  = (idx / MAPD) % MAPD;
    int f  = (idx / NPIX) % FCH;
    int b  = idx / (NPIX*FCH);
    float v = 0.0f;
    if (y >= 50 && y <= 74 && x >= 50 && x <= 74)
        v = g_rot[((b*NA + 0)*FCH + f)*KSZ + (y-50)*LOCD + (x-50)];
    g_oreg[idx] = v;
}

// ---------------------------------------------------------------------------
// Unified tensor-core correlation kernel (bf16 hi/lo split, mma.sync m16n8k16).
// Rolling A-fragment register cache across ky: only one new A row (10 LDS)
// per ky, shared by both kxh halves; B repacked for LDS.64.
// ---------------------------------------------------------------------------
__global__ __launch_bounds__(256, 2)
void convmma_kernel(const float* __restrict__ planes, int nplanes,
                    const float* __restrict__ wts,
                    int mode, int OC,
                    float* __restrict__ outp)
{
    extern __shared__ char sm[];
    unsigned short* AhiE = (unsigned short*)sm;          // [AROWS*TAW]
    unsigned short* AhiO = AhiE + AROWS*TAW;
    unsigned short* AloE = AhiO + AROWS*TAW;
    unsigned short* AloO = AloE + AROWS*TAW;
    uint2* Bh2 = (uint2*)(sm + 4*AROWS*TAW*2);           // [NB2]
    uint2* Bl2 = Bh2 + NB2;
    const uint32_t* AhiE32 = (const uint32_t*)AhiE;
    const uint32_t* AhiO32 = (const uint32_t*)AhiO;
    const uint32_t* AloE32 = (const uint32_t*)AloE;
    const uint32_t* AloO32 = (const uint32_t*)AloO;

    const int tid  = threadIdx.x;
    const int warp = tid >> 5;
    const int lane = tid & 31;
    const int g    = lane >> 2;          // group id
    const int q    = lane & 3;           // thread-in-group
    const int x0   = warp * 16;          // M-tile base
    const int yg   = blockIdx.x;
    const int fg   = blockIdx.y;
    const int b    = blockIdx.z;
    const int y0   = yg * RY;
    const int pbase = x0 + g + 2*q;      // Toeplitz element base
    const int wo    = pbase >> 1;
    const int par   = pbase & 1;

    float acc[RY][4];
#pragma unroll
    for (int y = 0; y < RY; y++)
#pragma unroll
        for (int i = 0; i < 4; i++) acc[y][i] = 0.0f;

    const uint32_t* Ah = par ? AhiO32 : AhiE32;
    const uint32_t* Al = par ? AloO32 : AloE32;

    for (int ci = 0; ci < nplanes; ci++) {
        __syncthreads();   // previous iteration's smem reads complete

        // ---- A fill: rows y0-12 .. y0+15, elements e=gx+12 in [0,160) ----
        const float* src = planes + (b*nplanes + ci)*NPIX;
        for (int idx = tid; idx < AROWS*TAW; idx += 256) {
            int r = idx / TAW, e = idx - r*TAW;
            int gy = y0 - 12 + r, gx = e - 12;
            float v = (gy >= 0 && gy < MAPD && gx >= 0 && gx < MAPD)
                      ? src[gy*MAPD + gx] : 0.0f;
            unsigned short h, l;
            split2(v, h, l);
            AhiE[idx] = h; AloE[idx] = l;
            if (e > 0) { AhiO[idx-1] = h; AloO[idx-1] = l; }
        }

        // ---- B fill: uint2 [ky][kxh][g][q] = ( word(j=q,n=g), word(j=q+4,n=g) )
        //      word = bf16 pair (w(kx0), w(kx0+1)), kx0 = kxh*16 + 2j
        for (int i = tid; i < NB2; i += 256) {
            int fq  = i & 3;
            int fgd = (i >> 2) & 7;
            int kxh = (i >> 5) & 1;
            int ky  = i >> 6;
            uint32_t hw[2], lw[2];
#pragma unroll
            for (int m = 0; m < 2; m++) {
                int j   = fq + 4*m;
                int kx0 = kxh*16 + 2*j;
                float w0 = 0.0f, w1 = 0.0f;
                if (mode == 0) {
                    const float* wb = wts + ((b*NA + fgd)*FCH + (ci+1))*KSZ + ky*LOCD;
                    if (kx0   < LOCD) w0 = wb[kx0];
                    if (kx0+1 < LOCD) w1 = wb[kx0+1];
                } else {
                    const float* wb = wts + ((b*NA + ci)*FCH + (fg*8 + fgd))*KSZ + (24-ky)*LOCD;
                    if (kx0   < LOCD) w0 = wb[24-kx0];
                    if (kx0+1 < LOCD) w1 = wb[24-(kx0+1)];
                }
                unsigned short h0, l0, h1, l1;
                split2(w0, h0, l0);
                split2(w1, h1, l1);
                hw[m] = (uint32_t)h0 | ((uint32_t)h1 << 16);
                lw[m] = (uint32_t)l0 | ((uint32_t)l1 << 16);
            }
            Bh2[i] = make_uint2(hw[0], hw[1]);
            Bl2[i] = make_uint2(lw[0], lw[1]);
        }
        __syncthreads();

        // ---- MMA loop with rolling A-row register cache ----
        uint32_t ahi[4][5], alo[4][5];
        // preload rows 0..2 into slots 0..2
#pragma unroll
        for (int r = 0; r < 3; r++) {
            int base = r*(TAW/2) + wo;
#pragma unroll
            for (int w = 0; w < 5; w++) {
                ahi[r][w] = Ah[base + 4*w];
                alo[r][w] = Al[base + 4*w];
            }
        }

#pragma unroll
        for (int ky = 0; ky < LOCD; ky++) {
            // load row ky+3 into slot (ky+3)&3
            {
                int s = (ky+3) & 3;
                int base = (ky+3)*(TAW/2) + wo;
#pragma unroll
                for (int w = 0; w < 5; w++) {
                    ahi[s][w] = Ah[base + 4*w];
                    alo[s][w] = Al[base + 4*w];
                }
            }
#pragma unroll
            for (int kxh = 0; kxh < 2; kxh++) {
                int bidx = (ky*2 + kxh)*32 + g*4 + q;
                uint2 bh = Bh2[bidx];
                uint2 bl = Bl2[bidx];
                int k0 = kxh*2;
#pragma unroll
                for (int y = 0; y < RY; y++) {
                    int s = (ky + y) & 3;
                    uint32_t h0 = ahi[s][k0], h1 = ahi[s][k0+1], h2 = ahi[s][k0+2];
                    uint32_t l0 = alo[s][k0], l1 = alo[s][k0+1], l2 = alo[s][k0+2];
                    mma_bf16(acc[y], h0, h1, h1, h2, bh.x, bh.y);   // hi*hi
                    mma_bf16(acc[y], h0, h1, h1, h2, bl.x, bl.y);   // hi*lo
                    mma_bf16(acc[y], l0, l1, l1, l2, bh.x, bh.y);   // lo*hi
                }
            }
        }
    }

    // ---- epilogue: D rows g/g+8, cols 2q/2q+1 ----
#pragma unroll
    for (int y = 0; y < RY; y++) {
        int gy = y0 + y;
        if (gy >= MAPD) continue;
        float* ob = outp + (b*OC + fg*8)*NPIX + gy*MAPD;
        int n0 = 2*q;
        int x1 = x0 + g;
        ob[n0*NPIX + x1]     = acc[y][0];
        ob[(n0+1)*NPIX + x1] = acc[y][1];
        int x2 = x1 + 8;
        if (x2 < MAPD) {
            ob[n0*NPIX + x2]     = acc[y][2];
            ob[(n0+1)*NPIX + x2] = acc[y][3];
        }
    }
}

// ---------------------------------------------------------------------------
// GRU cell per pixel + channel softmax.
// ---------------------------------------------------------------------------
__global__ __launch_bounds__(128)
void gru_kernel(const float* __restrict__ hprev,
                const float* __restrict__ w_ih, const float* __restrict__ w_hh,
                const float* __restrict__ b_ih, const float* __restrict__ b_hh,
                float* __restrict__ mout)
{
    __shared__ float4 s_wih[96*8];
    __shared__ float4 s_whh[96*8];
    __shared__ float  s_b[192];

    const int tid = threadIdx.x;
    const float4* wi4 = (const float4*)w_ih;
    const float4* wh4 = (const float4*)w_hh;
    for (int i = tid; i < 96*8; i += 128) { s_wih[i] = wi4[i]; s_whh[i] = wh4[i]; }
    if (tid < 96) { s_b[tid] = b_ih[tid]; s_b[96+tid] = b_hh[tid]; }
    __syncthreads();

    const int pix = blockIdx.x * 128 + tid;
    if (pix >= NPIX) return;
    const int b = blockIdx.y;

    float x[32], h[32];
#pragma unroll
    for (int c = 0; c < 32; c++) {
        x[c] = g_oreg[(b*FCH + c)*NPIX + pix];
        h[c] = hprev[(b*FCH + c)*NPIX + pix];
    }

    float mx = -1e30f;
    float mvals[32];
    for (int c = 0; c < 32; c++) {
        float accr = s_b[c]      + s_b[96+c];
        float accz = s_b[32+c]   + s_b[128+c];
        float acci = s_b[64+c];
        float acch = s_b[160+c];
        const float4* wr_i = s_wih + c*8;
        const float4* wz_i = s_wih + (32+c)*8;
        const float4* wn_i = s_wih + (64+c)*8;
        const float4* wr_h = s_whh + c*8;
        const float4* wz_h = s_whh + (32+c)*8;
        const float4* wn_h = s_whh + (64+c)*8;
#pragma unroll
        for (int k = 0; k < 8; k++) {
            float4 wv;
            wv = wr_i[k]; accr += wv.x*x[4*k] + wv.y*x[4*k+1] + wv.z*x[4*k+2] + wv.w*x[4*k+3];
            wv = wr_h[k]; accr += wv.x*h[4*k] + wv.y*h[4*k+1] + wv.z*h[4*k+2] + wv.w*h[4*k+3];
            wv = wz_i[k]; accz += wv.x*x[4*k] + wv.y*x[4*k+1] + wv.z*x[4*k+2] + wv.w*x[4*k+3];
            wv = wz_h[k]; accz += wv.x*h[4*k] + wv.y*h[4*k+1] + wv.z*h[4*k+2] + wv.w*h[4*k+3];
            wv = wn_i[k]; acci += wv.x*x[4*k] + wv.y*x[4*k+1] + wv.z*x[4*k+2] + wv.w*x[4*k+3];
            wv = wn_h[k]; acch += wv.x*h[4*k] + wv.y*h[4*k+1] + wv.z*h[4*k+2] + wv.w*h[4*k+3];
        }
        float r = 1.0f/(1.0f + expf(-accr));
        float z = 1.0f/(1.0f + expf(-accz));
        float n = tanhf(acci + r*acch);
        float mv = (1.0f - z)*n + z*h[c];
        mvals[c] = mv;
        mout[(b*FCH + c)*NPIX + pix] = mv;
        mx = fmaxf(mx, mv);
    }

    float sum = 0.0f;
    float e[32];
#pragma unroll
    for (int c = 0; c < 32; c++) { e[c] = expf(mvals[c] - mx); sum += e[c]; }
    float inv = 1.0f / sum;
#pragma unroll
    for (int c = 1; c < 32; c++)
        g_msm[(b*(FCH-1) + (c-1))*NPIX + pix] = e[c] * inv;
}

// ---------------------------------------------------------------------------
// Global softmax over (A,H,W) from g_scores.
// ---------------------------------------------------------------------------
__global__ void softmax_pose_kernel(float* __restrict__ pdst)
{
    const int b = blockIdx.x;
    const float* s = g_scores + b*NA*NPIX;
    float* o = pdst + b*NA*NPIX;
    const int N = NA*NPIX;
    __shared__ float red[33];
    const int tid = threadIdx.x;

    float mx = -1e30f;
    for (int i = tid; i < N; i += 1024) mx = fmaxf(mx, s[i]);
#pragma unroll
    for (int off = 16; off; off >>= 1) mx = fmaxf(mx, __shfl_xor_sync(0xffffffffu, mx, off));
    if ((tid & 31) == 0) red[tid >> 5] = mx;
    __syncthreads();
    if (tid < 32) {
        float v = red[tid];
#pragma unroll
        for (int off = 16; off; off >>= 1) v = fmaxf(v, __shfl_xor_sync(0xffffffffu, v, off));
        if (tid == 0) red[32] = v;
    }
    __syncthreads();
    mx = red[32];
    __syncthreads();

    float sum = 0.0f;
    for (int i = tid; i < N; i += 1024) sum += expf(s[i] - mx);
#pragma unroll
    for (int off = 16; off; off >>= 1) sum += __shfl_xor_sync(0xffffffffu, sum, off);
    if ((tid & 31) == 0) red[tid >> 5] = sum;
    __syncthreads();
    if (tid < 32) {
        float v = red[tid];
#pragma unroll
        for (int off = 16; off; off >>= 1) v += __shfl_xor_sync(0xffffffffu, v, off);
        if (tid == 0) red[32] = v;
    }
    __syncthreads();
    float inv = 1.0f / red[32];

    for (int i = tid; i < N; i += 1024) o[i] = expf(s[i] - mx) * inv;
}

// ---------------------------------------------------------------------------
// Host launcher (graph-capturable, allocation-free).
// Output: poses_all (5,8,8,125,125) | maps_all (5,8,32,125,125) | m_final (8,32,125,125)
// ---------------------------------------------------------------------------
extern "C" void kernel_launch(void* const* d_in, const int* in_sizes, int n_in,
                              void* d_out, int out_size)
{
    const float* img   = (const float*)d_in[0];
    const float* maps0 = (const float*)d_in[1];
    const float* w_ih  = (const float*)d_in[3];
    const float* w_hh  = (const float*)d_in[4];
    const float* b_ih  = (const float*)d_in[5];
    const float* b_hh  = (const float*)d_in[6];

    float* out   = (float*)d_out;
    float* poses = out;
    float* mapso = out + 5*BSZ*NA*NPIX;
    float* mfin  = out + 5*BSZ*NA*NPIX + 5*BSZ*FCH*NPIX;

    float *d_rot, *d_msm, *d_oreg, *d_scores;
    cudaGetSymbolAddress((void**)&d_rot,    g_rot);
    cudaGetSymbolAddress((void**)&d_msm,    g_msm);
    cudaGetSymbolAddress((void**)&d_oreg,   g_oreg);
    cudaGetSymbolAddress((void**)&d_scores, g_scores);

    cudaFuncSetAttribute(convmma_kernel, cudaFuncAttributeMaxDynamicSharedMemorySize, SMEMSZ);

    resample_kernel<<<(LL*ROTCH + 255)/256, 256>>>(img);

    for (int t = 0; t < LL-1; t++) {
        const float* hsrc = (t == 0) ? maps0 : (mapso + (t-1)*BSZ*FCH*NPIX);
        float* mdst = mapso + t*BSZ*FCH*NPIX;
        float* pdst = poses + t*BSZ*NA*NPIX;

        if (t == 0) {
            conv1_t0_kernel<<<(BSZ*FCH*NPIX + 255)/256, 256>>>();
        } else {
            const float* psrc = poses + (t-1)*BSZ*NA*NPIX;
            convmma_kernel<<<dim3(NYG, 4, BSZ), 256, SMEMSZ>>>(
                psrc, NA, d_rot + (size_t)t*ROTCH, 1, FCH, d_oreg);
        }
        gru_kernel<<<dim3((NPIX + 127)/128, BSZ), 128>>>(hsrc, w_ih, w_hh, b_ih, b_hh, mdst);
        convmma_kernel<<<dim3(NYG, 1, BSZ), 256, SMEMSZ>>>(
            d_msm, FCH-1, d_rot + (size_t)(t+1)*ROTCH, 0, NA, d_scores);
        softmax_pose_kernel<<<BSZ, 1024>>>(pdst);
    }

    cudaMemcpyAsync(mfin, mapso + 4*BSZ*FCH*NPIX,
                    (size_t)BSZ*FCH*NPIX*sizeof(float),
                    cudaMemcpyDeviceToDevice);
}